// round 12
// baseline (speedup 1.0000x reference)
#include <cuda_runtime.h>
#include <cuda_fp16.h>
#include <math.h>
#include <stdint.h>

#define BB 32
#define TT 512
#define II 512
#define HH 1024
#define RR 512

#define NBLK 136
#define NTHR 256

// smem: A tile 96 atoms x 2KB = 192KB @0 | red @196608
#define RED_OFF  196608
#define RED_STRIDE 33
#define RED_TILE   (32 * RED_STRIDE)
#define DSMEM (RED_OFF + 8 * RED_TILE * 4)   // 230400 <= 231424 opt-in cap

// ---------------------------------------------------------------------------
// Global scratch (device globals; no allocations anywhere)
// ---------------------------------------------------------------------------
__device__ __align__(16) unsigned char g_xImg[(size_t)TT * 32768];     // x B-frag imgs
__device__ __align__(16) unsigned char g_WhhF[(size_t)4 * 64 * 65536]; // Whh hi/lo A-frag (16MB)
__device__ __align__(16) unsigned char g_wpB[(size_t)2 * 1048576];     // Wp B-frag imgs for fold
__device__ __align__(16) unsigned char g_Wp1F[(size_t)8 * 131072];     // Wp1 A-frag tiles (1MB)
__device__ __align__(16) unsigned char g_m0Img[2][65536];              // m0 (parity)
__device__ __align__(16) unsigned char g_h0Img[2][32768];              // h0 (parity)
__device__ __align__(16) unsigned char g_m1Hist[(size_t)TT * 65536];   // m1 history (32MB)
__device__ __align__(16) unsigned char g_mZero[65536];                 // zero image

__device__ unsigned g_bar_count = 0;
__device__ volatile unsigned g_bar_gen = 0;

// ---------------------------------------------------------------------------
// Helpers
// ---------------------------------------------------------------------------
__device__ __forceinline__ uint32_t smem_u32(const void* p) {
    uint32_t a;
    asm("{ .reg .u64 t; cvta.to.shared.u64 t, %1; cvt.u32.u64 %0, t; }" : "=r"(a) : "l"(p));
    return a;
}
__device__ __forceinline__ void cp16(uint32_t d, const void* s) {
    asm volatile("cp.async.cg.shared.global [%0], [%1], 16;" :: "r"(d), "l"(s) : "memory");
}
__device__ __forceinline__ void cp_commit() { asm volatile("cp.async.commit_group;" ::: "memory"); }
template <int N>
__device__ __forceinline__ void cp_wait() { asm volatile("cp.async.wait_group %0;" :: "n"(N) : "memory"); }
__device__ __forceinline__ uint4 lds128(uint32_t a) {
    uint4 v;
    asm volatile("ld.shared.v4.u32 {%0,%1,%2,%3}, [%4];"
                 : "=r"(v.x), "=r"(v.y), "=r"(v.z), "=r"(v.w) : "r"(a));
    return v;
}
__device__ __forceinline__ void sts128(uint32_t a, uint4 v) {
    asm volatile("st.shared.v4.u32 [%0], {%1,%2,%3,%4};"
                 :: "r"(a), "r"(v.x), "r"(v.y), "r"(v.z), "r"(v.w) : "memory");
}
__device__ __forceinline__ uint2 ldg64cg(const void* p) {
    uint2 v;
    asm volatile("ld.global.cg.v2.u32 {%0,%1}, [%2];" : "=r"(v.x), "=r"(v.y) : "l"(p));
    return v;
}
__device__ __forceinline__ uint4 ldg128cg(const void* p) {
    uint4 v;
    asm volatile("ld.global.cg.v4.u32 {%0,%1,%2,%3}, [%4];"
                 : "=r"(v.x), "=r"(v.y), "=r"(v.z), "=r"(v.w) : "l"(p));
    return v;
}
__device__ __forceinline__ void mma16816(float* c, const uint4& a, const uint2& b) {
    asm volatile(
        "mma.sync.aligned.m16n8k16.row.col.f32.f16.f16.f32 "
        "{%0,%1,%2,%3}, {%4,%5,%6,%7}, {%8,%9}, {%0,%1,%2,%3};"
        : "+f"(c[0]), "+f"(c[1]), "+f"(c[2]), "+f"(c[3])
        : "r"(a.x), "r"(a.y), "r"(a.z), "r"(a.w), "r"(b.x), "r"(b.y));
}
__device__ __forceinline__ uint32_t pack2h(float a, float b) {
    __half2 h = __floats2half2_rn(a, b);
    return *(uint32_t*)&h;
}
__device__ __forceinline__ void grid_barrier() {
    __syncthreads();
    if (threadIdx.x == 0) {
        unsigned gen = g_bar_gen;
        __threadfence();
        if (atomicAdd(&g_bar_count, 1u) == NBLK - 1u) {
            g_bar_count = 0;
            __threadfence();
            g_bar_gen = gen + 1u;
        } else {
            while (g_bar_gen == gen) { __nanosleep(32); }
        }
        __threadfence();
    }
    __syncthreads();
}
// B-fragment-order half image offset for (k, col)
__device__ __forceinline__ uint32_t bimg_off(int k, int b) {
    const int ch = k >> 4, kk = k & 15;
    return ((uint32_t)(ch * 4 + (b >> 3)) * 32 + ((b & 7) * 4 + ((kk & 7) >> 1))) * 8
           + ((kk & 1) + 2 * (kk >> 3)) * 2;
}

// ---------------------------------------------------------------------------
// Gates GEMM: D[64,32], K=1536 (96 atoms; 0..31 from bA, 32..95 from bB).
// Warp = (mh, kq); 24 k-atoms per warp; depth-6 B register ring.
// ---------------------------------------------------------------------------
__device__ __forceinline__ const unsigned char* gsel(const unsigned char* bA,
                                                     const unsigned char* bB, int c) {
    c = (c < 96) ? c : 95;
    return (c < 32) ? (bA + c * 1024) : (bB + (c - 32) * 1024);
}

__device__ __forceinline__ void gemm_g(uint32_t smA, float* red,
                                       const unsigned char* bA,
                                       const unsigned char* bB,
                                       int wid, int lane)
{
    const int mh = wid >> 2, kq = wid & 3;
    const int c0 = kq * 24;
    const uint32_t abase = smA + c0 * 2048 + mh * 1024 + lane * 16;
    const uint32_t loff = lane * 8;

    float acc[2][4][4];
    #pragma unroll
    for (int m = 0; m < 2; ++m)
        #pragma unroll
        for (int n = 0; n < 4; ++n)
            #pragma unroll
            for (int i = 0; i < 4; ++i) acc[m][n][i] = 0.f;

    uint2 ring[6][4];
    #pragma unroll
    for (int i = 0; i < 6; ++i) {
        const unsigned char* p = gsel(bA, bB, c0 + i) + loff;
        #pragma unroll
        for (int n = 0; n < 4; ++n) ring[i][n] = ldg64cg(p + n * 256);
    }

    #pragma unroll
    for (int i = 0; i < 24; ++i) {
        const uint2 b0 = ring[i % 6][0], b1 = ring[i % 6][1];
        const uint2 b2 = ring[i % 6][2], b3 = ring[i % 6][3];
        if (i < 18) {
            const unsigned char* p = gsel(bA, bB, c0 + i + 6) + loff;
            #pragma unroll
            for (int n = 0; n < 4; ++n) ring[i % 6][n] = ldg64cg(p + n * 256);
        }
        const uint4 A0 = lds128(abase + i * 2048);
        const uint4 A1 = lds128(abase + i * 2048 + 512);
        mma16816(acc[0][0], A0, b0); mma16816(acc[1][0], A1, b0);
        mma16816(acc[0][1], A0, b1); mma16816(acc[1][1], A1, b1);
        mma16816(acc[0][2], A0, b2); mma16816(acc[1][2], A1, b2);
        mma16816(acc[0][3], A0, b3); mma16816(acc[1][3], A1, b3);
    }

    float* base = red + (mh * 4 + kq) * RED_TILE;
    const int r0 = lane >> 2, col0 = (lane & 3) * 2;
    #pragma unroll
    for (int mi = 0; mi < 2; ++mi)
        #pragma unroll
        for (int n = 0; n < 4; ++n) {
            const int row = mi * 16 + r0, col = n * 8 + col0;
            base[row * RED_STRIDE + col]           = acc[mi][n][0];
            base[row * RED_STRIDE + col + 1]       = acc[mi][n][1];
            base[(row + 8) * RED_STRIDE + col]     = acc[mi][n][2];
            base[(row + 8) * RED_STRIDE + col + 1] = acc[mi][n][3];
        }
}

// ---------------------------------------------------------------------------
// 64-atom GEMM (P0 / final out): D[64,32], K=1024, single B image.
// ---------------------------------------------------------------------------
__device__ __forceinline__ void gemm_16(uint32_t smA, float* red,
                                        const unsigned char* bimg,
                                        int wid, int lane)
{
    const int mh = wid >> 2, kq = wid & 3;
    const int c0 = kq * 16;
    const uint32_t abase = smA + c0 * 2048 + mh * 1024 + lane * 16;
    const uint32_t loff = lane * 8;

    float acc[2][4][4];
    #pragma unroll
    for (int m = 0; m < 2; ++m)
        #pragma unroll
        for (int n = 0; n < 4; ++n)
            #pragma unroll
            for (int i = 0; i < 4; ++i) acc[m][n][i] = 0.f;

    uint2 ring[6][4];
    #pragma unroll
    for (int i = 0; i < 6; ++i) {
        const int c = (c0 + i < 64) ? (c0 + i) : 63;
        #pragma unroll
        for (int n = 0; n < 4; ++n) ring[i][n] = ldg64cg(bimg + c * 1024 + loff + n * 256);
    }

    #pragma unroll
    for (int i = 0; i < 16; ++i) {
        const uint2 b0 = ring[i % 6][0], b1 = ring[i % 6][1];
        const uint2 b2 = ring[i % 6][2], b3 = ring[i % 6][3];
        if (i < 10) {
            const int c = (c0 + i + 6 < 64) ? (c0 + i + 6) : 63;
            #pragma unroll
            for (int n = 0; n < 4; ++n) ring[i % 6][n] = ldg64cg(bimg + c * 1024 + loff + n * 256);
        }
        const uint4 A0 = lds128(abase + i * 2048);
        const uint4 A1 = lds128(abase + i * 2048 + 512);
        mma16816(acc[0][0], A0, b0); mma16816(acc[1][0], A1, b0);
        mma16816(acc[0][1], A0, b1); mma16816(acc[1][1], A1, b1);
        mma16816(acc[0][2], A0, b2); mma16816(acc[1][2], A1, b2);
        mma16816(acc[0][3], A0, b3); mma16816(acc[1][3], A1, b3);
    }

    float* base = red + (mh * 4 + kq) * RED_TILE;
    const int r0 = lane >> 2, col0 = (lane & 3) * 2;
    #pragma unroll
    for (int mi = 0; mi < 2; ++mi)
        #pragma unroll
        for (int n = 0; n < 4; ++n) {
            const int row = mi * 16 + r0, col = n * 8 + col0;
            base[row * RED_STRIDE + col]           = acc[mi][n][0];
            base[row * RED_STRIDE + col + 1]       = acc[mi][n][1];
            base[(row + 8) * RED_STRIDE + col]     = acc[mi][n][2];
            base[(row + 8) * RED_STRIDE + col + 1] = acc[mi][n][3];
        }
}

// ---------------------------------------------------------------------------
// Persistent kernel
// ---------------------------------------------------------------------------
__global__ void __launch_bounds__(NTHR)
lstm_fold(const float* __restrict__ x,
          const float* __restrict__ Wih0, const float* __restrict__ Whh0,
          const float* __restrict__ bias0, const float* __restrict__ Wp0,
          const float* __restrict__ Wih1, const float* __restrict__ Whh1,
          const float* __restrict__ bias1, const float* __restrict__ Wp1,
          float* __restrict__ out)
{
    extern __shared__ __align__(16) unsigned char smem[];
    const uint32_t smA = smem_u32(smem);
    float* red = (float*)(smem + RED_OFF);
    const int tid = threadIdx.x;
    const int blk = blockIdx.x;
    const int wid = tid >> 5;
    const int lane = tid & 31;
    const int gtid = blk * NTHR + tid;
    const int GT = NBLK * NTHR;

    // ===== prologue A: cooperative global packs =====
    // zero m0Img[1] + g_mZero (graph replay)
    for (int i = gtid; i < (65536 * 2) / 16; i += GT) {
        if (i < 65536 / 16) ((uint4*)g_m0Img[1])[i] = make_uint4(0, 0, 0, 0);
        else ((uint4*)g_mZero)[i - 65536 / 16] = make_uint4(0, 0, 0, 0);
    }
    // x -> B-frag images
    for (int idx = gtid; idx < 512 * 32 * 4 * 32; idx += GT) {
        const int ln = idx & 31, na = (idx >> 5) & 3, ch = (idx >> 7) & 31, t = idx >> 12;
        const int b = na * 8 + (ln >> 2);
        const int k0 = ch * 16 + (ln & 3) * 2;
        const float* sp = x + ((size_t)b * TT + t) * II + k0;
        const float2 lo = *(const float2*)sp;
        const float2 hi = *(const float2*)(sp + 8);
        uint2 o; o.x = pack2h(lo.x, lo.y); o.y = pack2h(hi.x, hi.y);
        *(uint2*)(g_xImg + ((((size_t)t * 32 + ch) * 4 + na) * 32 + ln) * 8) = o;
    }
    // Whh hi/lo A-frag tiles (rows rl = u*4+g)
    for (int idx = gtid; idx < (1 << 20); idx += GT) {
        const int ln = idx & 31, m = (idx >> 5) & 3, kc = (idx >> 7) & 31;
        const int mt = (idx >> 12) & 63, hl = (idx >> 18) & 1, layer = idx >> 19;
        const int rl = m * 16 + (ln >> 2);
        const int u = rl >> 2, g = rl & 3;
        const int grow = g * HH + mt * 16 + u;
        const int k0 = kc * 16 + (ln & 3) * 2;
        const float* W = layer ? Whh1 : Whh0;   // [4096 x 512]
        const float* p0 = W + (size_t)grow * RR + k0;
        const float* p1 = W + (size_t)(grow + 2) * RR + k0;
        float v[8] = { p0[0], p0[1], p1[0], p1[1], p0[8], p0[9], p1[8], p1[9] };
        uint32_t h[8];
        #pragma unroll
        for (int j = 0; j < 8; ++j) {
            __half hv = __float2half_rn(v[j]);
            if (hl) hv = __float2half_rn(v[j] - __half2float(hv));
            h[j] = (uint32_t)*(unsigned short*)&hv;
        }
        uint4 o;
        o.x = h[0] | (h[1] << 16); o.y = h[2] | (h[3] << 16);
        o.z = h[4] | (h[5] << 16); o.w = h[6] | (h[7] << 16);
        *(uint4*)(g_WhhF + ((size_t)((layer * 2 + hl) * 64 + mt)) * 65536
                  + ((kc * 4 + m) * 32 + ln) * 16) = o;
    }
    // Wp B-frag images for the fold (cols n = 0..1023, K rows = 512)
    for (int idx = gtid; idx < (1 << 18); idx += GT) {
        const int ln = idx & 31, na = (idx >> 5) & 127, ch = (idx >> 12) & 31, layer = idx >> 17;
        const int n = na * 8 + (ln >> 2);
        const int k0 = ch * 16 + (ln & 3) * 2;
        const float* Wp = layer ? Wp1 : Wp0;    // [512 x 1024]
        uint2 o;
        o.x = pack2h(Wp[(size_t)k0 * HH + n], Wp[(size_t)(k0 + 1) * HH + n]);
        o.y = pack2h(Wp[(size_t)(k0 + 8) * HH + n], Wp[(size_t)(k0 + 9) * HH + n]);
        *(uint2*)(g_wpB + (size_t)layer * 1048576 + (((size_t)ch * 128 + na) * 32 + ln) * 8) = o;
    }
    // Wp1 A-frag tiles (for the final out GEMM)
    for (int idx = gtid; idx < (1 << 16); idx += GT) {
        const int ln = idx & 31, m = (idx >> 5) & 3, kc = (idx >> 7) & 63, rt = idx >> 13;
        const int r = rt * 64 + m * 16 + (ln >> 2);
        const int k0 = kc * 16 + (ln & 3) * 2;
        const float* p0 = Wp1 + (size_t)r * HH + k0;
        const float* p1 = p0 + 8 * HH;
        uint4 o;
        o.x = pack2h(p0[0], p0[1]); o.y = pack2h(p1[0], p1[1]);
        o.z = pack2h(p0[8], p0[9]); o.w = pack2h(p1[8], p1[9]);
        *(uint4*)(g_Wp1F + (size_t)rt * 131072 + ((kc * 4 + m) * 32 + ln) * 16) = o;
    }

    grid_barrier();  // global packs visible chip-wide

    // ===== prologue B: per-CTA smem A tiles =====
    const bool isG = blk < 128;
    const int layer = (blk >> 6) & 1;
    const int mt = blk & 63;
    const int rt8 = blk - 128;          // P0 r-tile (0..7)

    if (isG) {
        // W_ih part -> atoms 0..31
        const float* W = layer ? Wih1 : Wih0;   // [4096 x 512]
        for (int idx = tid; idx < 32 * 4 * 32; idx += NTHR) {
            const int ln = idx & 31, m = (idx >> 5) & 3, kc = idx >> 7;
            const int rl = m * 16 + (ln >> 2);
            const int u = rl >> 2, g = rl & 3;
            const int grow = g * HH + mt * 16 + u;
            const int k0 = kc * 16 + (ln & 3) * 2;
            const float* p0 = W + (size_t)grow * RR + k0;
            const float* p1 = W + (size_t)(grow + 2) * RR + k0;
            uint4 o;
            o.x = pack2h(p0[0], p0[1]); o.y = pack2h(p1[0], p1[1]);
            o.z = pack2h(p0[8], p0[9]); o.w = pack2h(p1[8], p1[9]);
            sts128(smA + (kc * 4 + m) * 512 + ln * 16, o);
        }
        // fold: Whp = Whh_hi@Wp + Whh_lo@Wp -> atoms 32..95 (A read from global)
        const unsigned char* Ah = g_WhhF + ((size_t)(layer * 2 + 0) * 64 + mt) * 65536;
        const unsigned char* Al = g_WhhF + ((size_t)(layer * 2 + 1) * 64 + mt) * 65536;
        const unsigned char* Bb = g_wpB + (size_t)layer * 1048576;
        const int mh = wid >> 2, nq = wid & 3;
        for (int g4 = 0; g4 < 8; ++g4) {
            const int na0 = nq * 32 + g4 * 4;
            float acc[2][4][4];
            #pragma unroll
            for (int m = 0; m < 2; ++m)
                #pragma unroll
                for (int n = 0; n < 4; ++n)
                    #pragma unroll
                    for (int i = 0; i < 4; ++i) acc[m][n][i] = 0.f;
            for (int kc = 0; kc < 32; ++kc) {
                const uint4 ah0 = ldg128cg(Ah + ((kc * 4 + mh * 2) * 32 + lane) * 16);
                const uint4 ah1 = ldg128cg(Ah + ((kc * 4 + mh * 2 + 1) * 32 + lane) * 16);
                const uint4 al0 = ldg128cg(Al + ((kc * 4 + mh * 2) * 32 + lane) * 16);
                const uint4 al1 = ldg128cg(Al + ((kc * 4 + mh * 2 + 1) * 32 + lane) * 16);
                #pragma unroll
                for (int ns = 0; ns < 4; ++ns) {
                    const uint2 bv = ldg64cg(Bb + (((size_t)kc * 128 + na0 + ns) * 32 + lane) * 8);
                    mma16816(acc[0][ns], ah0, bv); mma16816(acc[1][ns], ah1, bv);
                    mma16816(acc[0][ns], al0, bv); mma16816(acc[1][ns], al1, bv);
                }
            }
            #pragma unroll
            for (int mi = 0; mi < 2; ++mi)
                #pragma unroll
                for (int p2 = 0; p2 < 2; ++p2) {
                    uint4 o;
                    o.x = pack2h(acc[mi][p2 * 2][0],     acc[mi][p2 * 2][1]);
                    o.y = pack2h(acc[mi][p2 * 2][2],     acc[mi][p2 * 2][3]);
                    o.z = pack2h(acc[mi][p2 * 2 + 1][0], acc[mi][p2 * 2 + 1][1]);
                    o.w = pack2h(acc[mi][p2 * 2 + 1][2], acc[mi][p2 * 2 + 1][3]);
                    const int atom = 32 + (na0 >> 1) + p2;
                    sts128(smA + (atom * 4 + mh * 2 + mi) * 512 + lane * 16, o);
                }
        }
    } else {
        // P0: Wp0 rows rt8*64.. -> atoms 0..63
        for (int idx = tid; idx < 64 * 4 * 32; idx += NTHR) {
            const int ln = idx & 31, m = (idx >> 5) & 3, kc = idx >> 7;
            const int r = rt8 * 64 + m * 16 + (ln >> 2);
            const int k0 = kc * 16 + (ln & 3) * 2;
            const float* p0 = Wp0 + (size_t)r * HH + k0;
            const float* p1 = p0 + 8 * HH;
            uint4 o;
            o.x = pack2h(p0[0], p0[1]); o.y = pack2h(p1[0], p1[1]);
            o.z = pack2h(p0[8], p0[9]); o.w = pack2h(p1[8], p1[9]);
            sts128(smA + (kc * 4 + m) * 512 + ln * 16, o);
        }
    }
    __syncthreads();

    // bias + cell regs (G CTAs)
    float bc[4], creg[2];
    creg[0] = creg[1] = 0.f;
    const int eu = tid >> 4, eb0 = (tid & 15) * 2;
    if (isG) {
        const float* bias = layer ? bias1 : bias0;
        #pragma unroll
        for (int g = 0; g < 4; ++g) bc[g] = bias[g * HH + mt * 16 + eu];
    }

    grid_barrier();

    // ===== main recurrence: ONE barrier per tick =====
    // tick s: G0(t=s), G1(t=s-2), P0(t=s-1)
    for (int s = 0; s <= 513; ++s) {
        if (blk < 64) {                         // G0
            const int t = s;
            if (t < 512) {
                gemm_g(smA, red, g_xImg + (size_t)t * 32768, g_m0Img[(t + 1) & 1], wid, lane);
                __syncthreads();
                unsigned char* dst = g_m0Img[t & 1];
                const int U = mt * 16 + eu;
                #pragma unroll
                for (int pp = 0; pp < 2; ++pp) {
                    const int b = eb0 + pp;
                    float gv[4];
                    #pragma unroll
                    for (int g = 0; g < 4; ++g) {
                        const int rl = eu * 4 + g;
                        const float* tb = red + (rl >> 5) * 4 * RED_TILE + (rl & 31) * RED_STRIDE + b;
                        gv[g] = bc[g] + tb[0] + tb[RED_TILE] + tb[2 * RED_TILE] + tb[3 * RED_TILE];
                    }
                    const float ig = 1.f / (1.f + expf(-gv[0]));
                    const float fg = 1.f / (1.f + expf(-gv[1]));
                    const float gg = tanhf(gv[2]);
                    const float og = 1.f / (1.f + expf(-gv[3]));
                    const float c = fg * creg[pp] + ig * gg;
                    creg[pp] = c;
                    *(__half*)(dst + bimg_off(U, b)) = __float2half_rn(og * tanhf(c));
                }
            }
        } else if (blk < 128) {                 // G1
            const int t = s - 2;
            if (t >= 0 && t < 512) {
                const unsigned char* bB = t ? (g_m1Hist + (size_t)(t - 1) * 65536) : g_mZero;
                gemm_g(smA, red, g_h0Img[t & 1], bB, wid, lane);
                __syncthreads();
                unsigned char* dst = g_m1Hist + (size_t)t * 65536;
                const int U = mt * 16 + eu;
                #pragma unroll
                for (int pp = 0; pp < 2; ++pp) {
                    const int b = eb0 + pp;
                    float gv[4];
                    #pragma unroll
                    for (int g = 0; g < 4; ++g) {
                        const int rl = eu * 4 + g;
                        const float* tb = red + (rl >> 5) * 4 * RED_TILE + (rl & 31) * RED_STRIDE + b;
                        gv[g] = bc[g] + tb[0] + tb[RED_TILE] + tb[2 * RED_TILE] + tb[3 * RED_TILE];
                    }
                    const float ig = 1.f / (1.f + expf(-gv[0]));
                    const float fg = 1.f / (1.f + expf(-gv[1]));
                    const float gg = tanhf(gv[2]);
                    const float og = 1.f / (1.f + expf(-gv[3]));
                    const float c = fg * creg[pp] + ig * gg;
                    creg[pp] = c;
                    *(__half*)(dst + bimg_off(U, b)) = __float2half_rn(og * tanhf(c));
                }
            }
        } else {                                // P0
            const int t = s - 1;
            if (t >= 0 && t < 512) {
                gemm_16(smA, red, g_m0Img[t & 1], wid, lane);
                __syncthreads();
                unsigned char* dst = g_h0Img[t & 1];
                const int rl = tid >> 2, bq = (tid & 3) * 8;
                const float* tb0 = red + (rl >> 5) * 4 * RED_TILE + (rl & 31) * RED_STRIDE;
                const int rg = rt8 * 64 + rl;
                #pragma unroll
                for (int j = 0; j < 8; ++j) {
                    const int b = bq + j;
                    const float v = tb0[b] + tb0[RED_TILE + b]
                                  + tb0[2 * RED_TILE + b] + tb0[3 * RED_TILE + b];
                    *(__half*)(dst + bimg_off(rg, b)) = __float2half_rn(v);
                }
            }
        }
        grid_barrier();
    }

    // ===== final: out[b][t][r] = Wp1 . m1Hist[t], 8 r-tiles x 17 t-stripes =====
    const int frt = blk & 7;
    const int ft0 = blk >> 3;               // 0..16
    {
        const unsigned char* src = g_Wp1F + (size_t)frt * 131072;
        for (int i = tid; i < 8192; i += NTHR) cp16(smA + i * 16, src + (size_t)i * 16);
        cp_commit(); cp_wait<0>();
        __syncthreads();
    }
    for (int t = ft0; t < 512; t += 17) {
        gemm_16(smA, red, g_m1Hist + (size_t)t * 65536, wid, lane);
        __syncthreads();
        const int rl = tid >> 2, bq = (tid & 3) * 8;
        const float* tb0 = red + (rl >> 5) * 4 * RED_TILE + (rl & 31) * RED_STRIDE;
        const int rg = frt * 64 + rl;
        #pragma unroll
        for (int j = 0; j < 8; ++j) {
            const int b = bq + j;
            const float v = tb0[b] + tb0[RED_TILE + b]
                          + tb0[2 * RED_TILE + b] + tb0[3 * RED_TILE + b];
            out[((size_t)b * TT + t) * RR + rg] = v;
        }
        __syncthreads();
    }
}

// ---------------------------------------------------------------------------
extern "C" void kernel_launch(void* const* d_in, const int* in_sizes, int n_in,
                              void* d_out, int out_size) {
    cudaFuncSetAttribute(lstm_fold, cudaFuncAttributeMaxDynamicSharedMemorySize, DSMEM);
    lstm_fold<<<NBLK, NTHR, DSMEM>>>(
        (const float*)d_in[0],
        (const float*)d_in[1], (const float*)d_in[2], (const float*)d_in[3], (const float*)d_in[4],
        (const float*)d_in[5], (const float*)d_in[6], (const float*)d_in[7], (const float*)d_in[8],
        (float*)d_out);
}

// round 13
// speedup vs baseline: 1.5314x; 1.5314x over previous
#include <cuda_runtime.h>
#include <cuda_fp16.h>
#include <math.h>
#include <stdint.h>

#define BB 32
#define TT 512
#define II 512
#define HH 1024
#define RR 512

#define NBLK 136
#define NTHR 256

// smem: A tile 96 atoms x 2KB = 192KB @0 | red @196608
#define RED_OFF  196608
#define RED_STRIDE 33
#define RED_TILE   (32 * RED_STRIDE)
#define DSMEM (RED_OFF + 8 * RED_TILE * 4)   // 230400 <= 231424 opt-in cap

// ---------------------------------------------------------------------------
// Global scratch (device globals; no allocations anywhere)
// ---------------------------------------------------------------------------
__device__ __align__(16) unsigned char g_xImg[(size_t)TT * 32768];     // x B-frag imgs
__device__ __align__(16) unsigned char g_WhhF[(size_t)4 * 64 * 65536]; // Whh hi/lo A-frag (16MB)
__device__ __align__(16) unsigned char g_wpB[(size_t)2 * 1048576];     // Wp B-frag imgs for fold
__device__ __align__(16) unsigned char g_Wp1F[(size_t)8 * 131072];     // Wp1 A-frag tiles (1MB)
__device__ __align__(16) unsigned char g_m0Img[2][65536];              // m0 (parity)
__device__ __align__(16) unsigned char g_h0Img[2][32768];              // h0 (parity)
__device__ __align__(16) unsigned char g_m1Hist[(size_t)TT * 65536];   // m1 history (32MB)
__device__ __align__(16) unsigned char g_mZero[65536];                 // zero image

// barriers
__device__ unsigned g_bar_count = 0;
__device__ volatile unsigned g_bar_gen = 0;
__device__ volatile unsigned g_flag[NBLK];
__device__ volatile unsigned g_release;

// ---------------------------------------------------------------------------
// Helpers
// ---------------------------------------------------------------------------
__device__ __forceinline__ uint32_t smem_u32(const void* p) {
    uint32_t a;
    asm("{ .reg .u64 t; cvta.to.shared.u64 t, %1; cvt.u32.u64 %0, t; }" : "=r"(a) : "l"(p));
    return a;
}
__device__ __forceinline__ void cp16(uint32_t d, const void* s) {
    asm volatile("cp.async.cg.shared.global [%0], [%1], 16;" :: "r"(d), "l"(s) : "memory");
}
__device__ __forceinline__ void cp_commit() { asm volatile("cp.async.commit_group;" ::: "memory"); }
template <int N>
__device__ __forceinline__ void cp_wait() { asm volatile("cp.async.wait_group %0;" :: "n"(N) : "memory"); }
__device__ __forceinline__ uint4 lds128(uint32_t a) {
    uint4 v;
    asm volatile("ld.shared.v4.u32 {%0,%1,%2,%3}, [%4];"
                 : "=r"(v.x), "=r"(v.y), "=r"(v.z), "=r"(v.w) : "r"(a));
    return v;
}
__device__ __forceinline__ void sts128(uint32_t a, uint4 v) {
    asm volatile("st.shared.v4.u32 [%0], {%1,%2,%3,%4};"
                 :: "r"(a), "r"(v.x), "r"(v.y), "r"(v.z), "r"(v.w) : "memory");
}
__device__ __forceinline__ uint2 ldg64cg(const void* p) {
    uint2 v;
    asm volatile("ld.global.cg.v2.u32 {%0,%1}, [%2];" : "=r"(v.x), "=r"(v.y) : "l"(p));
    return v;
}
__device__ __forceinline__ uint4 ldg128cg(const void* p) {
    uint4 v;
    asm volatile("ld.global.cg.v4.u32 {%0,%1,%2,%3}, [%4];"
                 : "=r"(v.x), "=r"(v.y), "=r"(v.z), "=r"(v.w) : "l"(p));
    return v;
}
__device__ __forceinline__ void mma16816(float* c, const uint4& a, const uint2& b) {
    asm volatile(
        "mma.sync.aligned.m16n8k16.row.col.f32.f16.f16.f32 "
        "{%0,%1,%2,%3}, {%4,%5,%6,%7}, {%8,%9}, {%0,%1,%2,%3};"
        : "+f"(c[0]), "+f"(c[1]), "+f"(c[2]), "+f"(c[3])
        : "r"(a.x), "r"(a.y), "r"(a.z), "r"(a.w), "r"(b.x), "r"(b.y));
}
__device__ __forceinline__ uint32_t pack2h(float a, float b) {
    __half2 h = __floats2half2_rn(a, b);
    return *(uint32_t*)&h;
}

// bootstrap barrier (atomic; proven replay-safe) — used ONCE per launch
__device__ __forceinline__ void grid_barrier_boot() {
    __syncthreads();
    if (threadIdx.x == 0) {
        unsigned gen = g_bar_gen;
        __threadfence();
        if (atomicAdd(&g_bar_count, 1u) == NBLK - 1u) {
            g_bar_count = 0;
            __threadfence();
            g_bar_gen = gen + 1u;
        } else {
            while (g_bar_gen == gen) { __nanosleep(32); }
        }
        __threadfence();
    }
    __syncthreads();
}

// fast flag-array barrier: arrival = 1 STG (no atomic contention);
// CTA0 aggregates with 136 parallel pollers, publishes release.
__device__ __forceinline__ void grid_barrier_fast(unsigned gen) {
    __syncthreads();
    if (threadIdx.x == 0) {
        __threadfence();
        g_flag[blockIdx.x] = gen;
    }
    if (blockIdx.x == 0) {
        if (threadIdx.x < NBLK) {
            while (g_flag[threadIdx.x] < gen) { __nanosleep(32); }
        }
        __syncthreads();
        if (threadIdx.x == 0) { __threadfence(); g_release = gen; }
    }
    if (threadIdx.x == 0) {
        while (g_release < gen) { __nanosleep(32); }
        __threadfence();
    }
    __syncthreads();
}

// B-fragment-order half image offset for (k, col)
__device__ __forceinline__ uint32_t bimg_off(int k, int b) {
    const int ch = k >> 4, kk = k & 15;
    return ((uint32_t)(ch * 4 + (b >> 3)) * 32 + ((b & 7) * 4 + ((kk & 7) >> 1))) * 8
           + ((kk & 1) + 2 * (kk >> 3)) * 2;
}

// ---------------------------------------------------------------------------
// Gates GEMM: D[64,32], K=1536 (96 atoms; 0..31 from bA, 32..95 from bB).
// Warp = (mh, kq); 24 k-atoms per warp; depth-8 B register ring.
// ---------------------------------------------------------------------------
__device__ __forceinline__ const unsigned char* gsel(const unsigned char* bA,
                                                     const unsigned char* bB, int c) {
    c = (c < 96) ? c : 95;
    return (c < 32) ? (bA + c * 1024) : (bB + (c - 32) * 1024);
}

__device__ __forceinline__ void gemm_g(uint32_t smA, float* red,
                                       const unsigned char* bA,
                                       const unsigned char* bB,
                                       int wid, int lane)
{
    const int mh = wid >> 2, kq = wid & 3;
    const int c0 = kq * 24;
    const uint32_t abase = smA + c0 * 2048 + mh * 1024 + lane * 16;
    const uint32_t loff = lane * 8;

    float acc[2][4][4];
    #pragma unroll
    for (int m = 0; m < 2; ++m)
        #pragma unroll
        for (int n = 0; n < 4; ++n)
            #pragma unroll
            for (int i = 0; i < 4; ++i) acc[m][n][i] = 0.f;

    uint2 ring[8][4];
    #pragma unroll
    for (int i = 0; i < 8; ++i) {
        const unsigned char* p = gsel(bA, bB, c0 + i) + loff;
        #pragma unroll
        for (int n = 0; n < 4; ++n) ring[i][n] = ldg64cg(p + n * 256);
    }

    #pragma unroll
    for (int i = 0; i < 24; ++i) {
        const uint2 b0 = ring[i & 7][0], b1 = ring[i & 7][1];
        const uint2 b2 = ring[i & 7][2], b3 = ring[i & 7][3];
        if (i < 16) {
            const unsigned char* p = gsel(bA, bB, c0 + i + 8) + loff;
            #pragma unroll
            for (int n = 0; n < 4; ++n) ring[i & 7][n] = ldg64cg(p + n * 256);
        }
        const uint4 A0 = lds128(abase + i * 2048);
        const uint4 A1 = lds128(abase + i * 2048 + 512);
        mma16816(acc[0][0], A0, b0); mma16816(acc[1][0], A1, b0);
        mma16816(acc[0][1], A0, b1); mma16816(acc[1][1], A1, b1);
        mma16816(acc[0][2], A0, b2); mma16816(acc[1][2], A1, b2);
        mma16816(acc[0][3], A0, b3); mma16816(acc[1][3], A1, b3);
    }

    float* base = red + (mh * 4 + kq) * RED_TILE;
    const int r0 = lane >> 2, col0 = (lane & 3) * 2;
    #pragma unroll
    for (int mi = 0; mi < 2; ++mi)
        #pragma unroll
        for (int n = 0; n < 4; ++n) {
            const int row = mi * 16 + r0, col = n * 8 + col0;
            base[row * RED_STRIDE + col]           = acc[mi][n][0];
            base[row * RED_STRIDE + col + 1]       = acc[mi][n][1];
            base[(row + 8) * RED_STRIDE + col]     = acc[mi][n][2];
            base[(row + 8) * RED_STRIDE + col + 1] = acc[mi][n][3];
        }
}

// ---------------------------------------------------------------------------
// 64-atom GEMM (P0 / final out): D[64,32], K=1024, single B image.
// Depth-8 ring (16 iters, prefetch distance 8).
// ---------------------------------------------------------------------------
__device__ __forceinline__ void gemm_16(uint32_t smA, float* red,
                                        const unsigned char* bimg,
                                        int wid, int lane)
{
    const int mh = wid >> 2, kq = wid & 3;
    const int c0 = kq * 16;
    const uint32_t abase = smA + c0 * 2048 + mh * 1024 + lane * 16;
    const uint32_t loff = lane * 8;

    float acc[2][4][4];
    #pragma unroll
    for (int m = 0; m < 2; ++m)
        #pragma unroll
        for (int n = 0; n < 4; ++n)
            #pragma unroll
            for (int i = 0; i < 4; ++i) acc[m][n][i] = 0.f;

    uint2 ring[8][4];
    #pragma unroll
    for (int i = 0; i < 8; ++i) {
        #pragma unroll
        for (int n = 0; n < 4; ++n)
            ring[i][n] = ldg64cg(bimg + (c0 + i) * 1024 + loff + n * 256);
    }

    #pragma unroll
    for (int i = 0; i < 16; ++i) {
        const uint2 b0 = ring[i & 7][0], b1 = ring[i & 7][1];
        const uint2 b2 = ring[i & 7][2], b3 = ring[i & 7][3];
        if (i < 8) {
            #pragma unroll
            for (int n = 0; n < 4; ++n)
                ring[i & 7][n] = ldg64cg(bimg + (c0 + i + 8) * 1024 + loff + n * 256);
        }
        const uint4 A0 = lds128(abase + i * 2048);
        const uint4 A1 = lds128(abase + i * 2048 + 512);
        mma16816(acc[0][0], A0, b0); mma16816(acc[1][0], A1, b0);
        mma16816(acc[0][1], A0, b1); mma16816(acc[1][1], A1, b1);
        mma16816(acc[0][2], A0, b2); mma16816(acc[1][2], A1, b2);
        mma16816(acc[0][3], A0, b3); mma16816(acc[1][3], A1, b3);
    }

    float* base = red + (mh * 4 + kq) * RED_TILE;
    const int r0 = lane >> 2, col0 = (lane & 3) * 2;
    #pragma unroll
    for (int mi = 0; mi < 2; ++mi)
        #pragma unroll
        for (int n = 0; n < 4; ++n) {
            const int row = mi * 16 + r0, col = n * 8 + col0;
            base[row * RED_STRIDE + col]           = acc[mi][n][0];
            base[row * RED_STRIDE + col + 1]       = acc[mi][n][1];
            base[(row + 8) * RED_STRIDE + col]     = acc[mi][n][2];
            base[(row + 8) * RED_STRIDE + col + 1] = acc[mi][n][3];
        }
}

// ---------------------------------------------------------------------------
// Persistent kernel.  Roles: blk 0..7 = P0 (light; blk0 aggregates barrier),
// blk 8..71 = G0 (layer 0), blk 72..135 = G1 (layer 1).
// ---------------------------------------------------------------------------
__global__ void __launch_bounds__(NTHR)
lstm_fold2(const float* __restrict__ x,
           const float* __restrict__ Wih0, const float* __restrict__ Whh0,
           const float* __restrict__ bias0, const float* __restrict__ Wp0,
           const float* __restrict__ Wih1, const float* __restrict__ Whh1,
           const float* __restrict__ bias1, const float* __restrict__ Wp1,
           float* __restrict__ out)
{
    extern __shared__ __align__(16) unsigned char smem[];
    const uint32_t smA = smem_u32(smem);
    float* red = (float*)(smem + RED_OFF);
    const int tid = threadIdx.x;
    const int blk = blockIdx.x;
    const int wid = tid >> 5;
    const int lane = tid & 31;
    const int gtid = blk * NTHR + tid;
    const int GT = NBLK * NTHR;

    // flag-barrier bootstrap: each CTA zeroes its own flag (visible after boot barrier)
    if (tid == 0) {
        g_flag[blk] = 0;
        if (blk == 0) g_release = 0;
    }

    // ===== prologue A: cooperative global packs =====
    for (int i = gtid; i < (65536 * 2) / 16; i += GT) {
        if (i < 65536 / 16) ((uint4*)g_m0Img[1])[i] = make_uint4(0, 0, 0, 0);
        else ((uint4*)g_mZero)[i - 65536 / 16] = make_uint4(0, 0, 0, 0);
    }
    // x -> B-frag images
    for (int idx = gtid; idx < 512 * 32 * 4 * 32; idx += GT) {
        const int ln = idx & 31, na = (idx >> 5) & 3, ch = (idx >> 7) & 31, t = idx >> 12;
        const int b = na * 8 + (ln >> 2);
        const int k0 = ch * 16 + (ln & 3) * 2;
        const float* sp = x + ((size_t)b * TT + t) * II + k0;
        const float2 lo = *(const float2*)sp;
        const float2 hi = *(const float2*)(sp + 8);
        uint2 o; o.x = pack2h(lo.x, lo.y); o.y = pack2h(hi.x, hi.y);
        *(uint2*)(g_xImg + ((((size_t)t * 32 + ch) * 4 + na) * 32 + ln) * 8) = o;
    }
    // Whh hi/lo A-frag tiles (rows rl = u*4+g)
    for (int idx = gtid; idx < (1 << 20); idx += GT) {
        const int ln = idx & 31, m = (idx >> 5) & 3, kc = (idx >> 7) & 31;
        const int mt = (idx >> 12) & 63, hl = (idx >> 18) & 1, layer = idx >> 19;
        const int rl = m * 16 + (ln >> 2);
        const int u = rl >> 2, g = rl & 3;
        const int grow = g * HH + mt * 16 + u;
        const int k0 = kc * 16 + (ln & 3) * 2;
        const float* W = layer ? Whh1 : Whh0;
        const float* p0 = W + (size_t)grow * RR + k0;
        const float* p1 = W + (size_t)(grow + 2) * RR + k0;
        float v[8] = { p0[0], p0[1], p1[0], p1[1], p0[8], p0[9], p1[8], p1[9] };
        uint32_t h[8];
        #pragma unroll
        for (int j = 0; j < 8; ++j) {
            __half hv = __float2half_rn(v[j]);
            if (hl) hv = __float2half_rn(v[j] - __half2float(hv));
            h[j] = (uint32_t)*(unsigned short*)&hv;
        }
        uint4 o;
        o.x = h[0] | (h[1] << 16); o.y = h[2] | (h[3] << 16);
        o.z = h[4] | (h[5] << 16); o.w = h[6] | (h[7] << 16);
        *(uint4*)(g_WhhF + ((size_t)((layer * 2 + hl) * 64 + mt)) * 65536
                  + ((kc * 4 + m) * 32 + ln) * 16) = o;
    }
    // Wp B-frag images for the fold
    for (int idx = gtid; idx < (1 << 18); idx += GT) {
        const int ln = idx & 31, na = (idx >> 5) & 127, ch = (idx >> 12) & 31, layer = idx >> 17;
        const int n = na * 8 + (ln >> 2);
        const int k0 = ch * 16 + (ln & 3) * 2;
        const float* Wp = layer ? Wp1 : Wp0;
        uint2 o;
        o.x = pack2h(Wp[(size_t)k0 * HH + n], Wp[(size_t)(k0 + 1) * HH + n]);
        o.y = pack2h(Wp[(size_t)(k0 + 8) * HH + n], Wp[(size_t)(k0 + 9) * HH + n]);
        *(uint2*)(g_wpB + (size_t)layer * 1048576 + (((size_t)ch * 128 + na) * 32 + ln) * 8) = o;
    }
    // Wp1 A-frag tiles (final out GEMM)
    for (int idx = gtid; idx < (1 << 16); idx += GT) {
        const int ln = idx & 31, m = (idx >> 5) & 3, kc = (idx >> 7) & 63, rt = idx >> 13;
        const int r = rt * 64 + m * 16 + (ln >> 2);
        const int k0 = kc * 16 + (ln & 3) * 2;
        const float* p0 = Wp1 + (size_t)r * HH + k0;
        const float* p1 = p0 + 8 * HH;
        uint4 o;
        o.x = pack2h(p0[0], p0[1]); o.y = pack2h(p1[0], p1[1]);
        o.z = pack2h(p0[8], p0[9]); o.w = pack2h(p1[8], p1[9]);
        *(uint4*)(g_Wp1F + (size_t)rt * 131072 + ((kc * 4 + m) * 32 + ln) * 16) = o;
    }

    grid_barrier_boot();   // packs visible + flags zeroed chip-wide

    // ===== prologue B: per-CTA smem A tiles =====
    const bool isG = blk >= 8;
    const int layer = isG ? ((blk - 8) >> 6) : 0;
    const int mt = (blk - 8) & 63;
    const int rt8 = blk;                 // P0 r-tile (0..7) for blk<8

    if (isG) {
        // W_ih part -> atoms 0..31
        const float* W = layer ? Wih1 : Wih0;
        for (int idx = tid; idx < 32 * 4 * 32; idx += NTHR) {
            const int ln = idx & 31, m = (idx >> 5) & 3, kc = idx >> 7;
            const int rl = m * 16 + (ln >> 2);
            const int u = rl >> 2, g = rl & 3;
            const int grow = g * HH + mt * 16 + u;
            const int k0 = kc * 16 + (ln & 3) * 2;
            const float* p0 = W + (size_t)grow * RR + k0;
            const float* p1 = W + (size_t)(grow + 2) * RR + k0;
            uint4 o;
            o.x = pack2h(p0[0], p0[1]); o.y = pack2h(p1[0], p1[1]);
            o.z = pack2h(p0[8], p0[9]); o.w = pack2h(p1[8], p1[9]);
            sts128(smA + (kc * 4 + m) * 512 + ln * 16, o);
        }
        // fold: Whp = Whh_hi@Wp + Whh_lo@Wp -> atoms 32..95
        const unsigned char* Ah = g_WhhF + ((size_t)(layer * 2 + 0) * 64 + mt) * 65536;
        const unsigned char* Al = g_WhhF + ((size_t)(layer * 2 + 1) * 64 + mt) * 65536;
        const unsigned char* Bb = g_wpB + (size_t)layer * 1048576;
        const int mh = wid >> 2, nq = wid & 3;
        for (int g4 = 0; g4 < 8; ++g4) {
            const int na0 = nq * 32 + g4 * 4;
            float acc[2][4][4];
            #pragma unroll
            for (int m = 0; m < 2; ++m)
                #pragma unroll
                for (int n = 0; n < 4; ++n)
                    #pragma unroll
                    for (int i = 0; i < 4; ++i) acc[m][n][i] = 0.f;
            for (int kc = 0; kc < 32; ++kc) {
                const uint4 ah0 = ldg128cg(Ah + ((kc * 4 + mh * 2) * 32 + lane) * 16);
                const uint4 ah1 = ldg128cg(Ah + ((kc * 4 + mh * 2 + 1) * 32 + lane) * 16);
                const uint4 al0 = ldg128cg(Al + ((kc * 4 + mh * 2) * 32 + lane) * 16);
                const uint4 al1 = ldg128cg(Al + ((kc * 4 + mh * 2 + 1) * 32 + lane) * 16);
                #pragma unroll
                for (int ns = 0; ns < 4; ++ns) {
                    const uint2 bv = ldg64cg(Bb + (((size_t)kc * 128 + na0 + ns) * 32 + lane) * 8);
                    mma16816(acc[0][ns], ah0, bv); mma16816(acc[1][ns], ah1, bv);
                    mma16816(acc[0][ns], al0, bv); mma16816(acc[1][ns], al1, bv);
                }
            }
            #pragma unroll
            for (int mi = 0; mi < 2; ++mi)
                #pragma unroll
                for (int p2 = 0; p2 < 2; ++p2) {
                    uint4 o;
                    o.x = pack2h(acc[mi][p2 * 2][0],     acc[mi][p2 * 2][1]);
                    o.y = pack2h(acc[mi][p2 * 2][2],     acc[mi][p2 * 2][3]);
                    o.z = pack2h(acc[mi][p2 * 2 + 1][0], acc[mi][p2 * 2 + 1][1]);
                    o.w = pack2h(acc[mi][p2 * 2 + 1][2], acc[mi][p2 * 2 + 1][3]);
                    const int atom = 32 + (na0 >> 1) + p2;
                    sts128(smA + (atom * 4 + mh * 2 + mi) * 512 + lane * 16, o);
                }
        }
    } else {
        // P0: Wp0 rows rt8*64.. -> atoms 0..63
        for (int idx = tid; idx < 64 * 4 * 32; idx += NTHR) {
            const int ln = idx & 31, m = (idx >> 5) & 3, kc = idx >> 7;
            const int r = rt8 * 64 + m * 16 + (ln >> 2);
            const int k0 = kc * 16 + (ln & 3) * 2;
            const float* p0 = Wp0 + (size_t)r * HH + k0;
            const float* p1 = p0 + 8 * HH;
            uint4 o;
            o.x = pack2h(p0[0], p0[1]); o.y = pack2h(p1[0], p1[1]);
            o.z = pack2h(p0[8], p0[9]); o.w = pack2h(p1[8], p1[9]);
            sts128(smA + (kc * 4 + m) * 512 + ln * 16, o);
        }
    }
    __syncthreads();

    // bias + cell regs (G CTAs)
    float bc[4], creg[2];
    creg[0] = creg[1] = 0.f;
    const int eu = tid >> 4, eb0 = (tid & 15) * 2;
    if (isG) {
        const float* bias = layer ? bias1 : bias0;
        #pragma unroll
        for (int g = 0; g < 4; ++g) bc[g] = bias[g * HH + mt * 16 + eu];
    }

    unsigned bgen = 1;
    grid_barrier_fast(bgen++);

    // ===== main recurrence: ONE fast barrier per tick =====
    // tick s: G0(t=s), G1(t=s-2), P0(t=s-1)
    for (int s = 0; s <= 513; ++s) {
        if (isG && layer == 0) {                // G0
            const int t = s;
            if (t < 512) {
                gemm_g(smA, red, g_xImg + (size_t)t * 32768, g_m0Img[(t + 1) & 1], wid, lane);
                __syncthreads();
                unsigned char* dst = g_m0Img[t & 1];
                const int U = mt * 16 + eu;
                #pragma unroll
                for (int pp = 0; pp < 2; ++pp) {
                    const int b = eb0 + pp;
                    float gv[4];
                    #pragma unroll
                    for (int g = 0; g < 4; ++g) {
                        const int rl = eu * 4 + g;
                        const float* tb = red + (rl >> 5) * 4 * RED_TILE + (rl & 31) * RED_STRIDE + b;
                        gv[g] = bc[g] + tb[0] + tb[RED_TILE] + tb[2 * RED_TILE] + tb[3 * RED_TILE];
                    }
                    const float ig = 1.f / (1.f + expf(-gv[0]));
                    const float fg = 1.f / (1.f + expf(-gv[1]));
                    const float gg = tanhf(gv[2]);
                    const float og = 1.f / (1.f + expf(-gv[3]));
                    const float c = fg * creg[pp] + ig * gg;
                    creg[pp] = c;
                    *(__half*)(dst + bimg_off(U, b)) = __float2half_rn(og * tanhf(c));
                }
            }
        } else if (isG) {                       // G1
            const int t = s - 2;
            if (t >= 0 && t < 512) {
                const unsigned char* bB = t ? (g_m1Hist + (size_t)(t - 1) * 65536) : g_mZero;
                gemm_g(smA, red, g_h0Img[t & 1], bB, wid, lane);
                __syncthreads();
                unsigned char* dst = g_m1Hist + (size_t)t * 65536;
                const int U = mt * 16 + eu;
                #pragma unroll
                for (int pp = 0; pp < 2; ++pp) {
                    const int b = eb0 + pp;
                    float gv[4];
                    #pragma unroll
                    for (int g = 0; g < 4; ++g) {
                        const int rl = eu * 4 + g;
                        const float* tb = red + (rl >> 5) * 4 * RED_TILE + (rl & 31) * RED_STRIDE + b;
                        gv[g] = bc[g] + tb[0] + tb[RED_TILE] + tb[2 * RED_TILE] + tb[3 * RED_TILE];
                    }
                    const float ig = 1.f / (1.f + expf(-gv[0]));
                    const float fg = 1.f / (1.f + expf(-gv[1]));
                    const float gg = tanhf(gv[2]);
                    const float og = 1.f / (1.f + expf(-gv[3]));
                    const float c = fg * creg[pp] + ig * gg;
                    creg[pp] = c;
                    *(__half*)(dst + bimg_off(U, b)) = __float2half_rn(og * tanhf(c));
                }
            }
        } else {                                // P0 (blk 0..7)
            const int t = s - 1;
            if (t >= 0 && t < 512) {
                gemm_16(smA, red, g_m0Img[t & 1], wid, lane);
                __syncthreads();
                unsigned char* dst = g_h0Img[t & 1];
                const int rl = tid >> 2, bq = (tid & 3) * 8;
                const float* tb0 = red + (rl >> 5) * 4 * RED_TILE + (rl & 31) * RED_STRIDE;
                const int rg = rt8 * 64 + rl;
                #pragma unroll
                for (int j = 0; j < 8; ++j) {
                    const int b = bq + j;
                    const float v = tb0[b] + tb0[RED_TILE + b]
                                  + tb0[2 * RED_TILE + b] + tb0[3 * RED_TILE + b];
                    *(__half*)(dst + bimg_off(rg, b)) = __float2half_rn(v);
                }
            }
        }
        grid_barrier_fast(bgen++);
    }

    // ===== final: out[b][t][r] = Wp1 . m1Hist[t], 8 r-tiles x 17 t-stripes =====
    const int frt = blk & 7;
    const int ft0 = blk >> 3;               // 0..16
    {
        const unsigned char* src = g_Wp1F + (size_t)frt * 131072;
        for (int i = tid; i < 8192; i += NTHR) cp16(smA + i * 16, src + (size_t)i * 16);
        cp_commit(); cp_wait<0>();
        __syncthreads();
    }
    for (int t = ft0; t < 512; t += 17) {
        gemm_16(smA, red, g_m1Hist + (size_t)t * 65536, wid, lane);
        __syncthreads();
        const int rl = tid >> 2, bq = (tid & 3) * 8;
        const float* tb0 = red + (rl >> 5) * 4 * RED_TILE + (rl & 31) * RED_STRIDE;
        const int rg = frt * 64 + rl;
        #pragma unroll
        for (int j = 0; j < 8; ++j) {
            const int b = bq + j;
            const float v = tb0[b] + tb0[RED_TILE + b]
                          + tb0[2 * RED_TILE + b] + tb0[3 * RED_TILE + b];
            out[((size_t)b * TT + t) * RR + rg] = v;
        }
        __syncthreads();
    }
}

// ---------------------------------------------------------------------------
extern "C" void kernel_launch(void* const* d_in, const int* in_sizes, int n_in,
                              void* d_out, int out_size) {
    cudaFuncSetAttribute(lstm_fold2, cudaFuncAttributeMaxDynamicSharedMemorySize, DSMEM);
    lstm_fold2<<<NBLK, NTHR, DSMEM>>>(
        (const float*)d_in[0],
        (const float*)d_in[1], (const float*)d_in[2], (const float*)d_in[3], (const float*)d_in[4],
        (const float*)d_in[5], (const float*)d_in[6], (const float*)d_in[7], (const float*)d_in[8],
        (float*)d_out);
}